// round 4
// baseline (speedup 1.0000x reference)
#include <cuda_runtime.h>
#include <cuda_bf16.h>
#include <cstdint>

#define BB 32
#define S_LEN 2048
#define EMB 256
#define NPOS (BB*S_LEN)
#define NSK 1000
#define NT64 32            // 64-col target tiles per sequence

// ---------- gathered operands (bf16, [pos][256]) ----------
__device__ __nv_bfloat16 g_srcA[NPOS*EMB];
__device__ __nv_bfloat16 g_srcB[NPOS*EMB];
__device__ __nv_bfloat16 g_tgtA[NPOS*EMB];
__device__ __nv_bfloat16 g_tgtB[NPOS*EMB];
__device__ float g_ts[NPOS];
__device__ float g_bias[NPOS];

// ---------- helpers ----------
__device__ __forceinline__ uint32_t smem_u32(const void* p){
    uint32_t a; asm("{ .reg .u64 t; cvta.to.shared.u64 t, %1; cvt.u32.u64 %0, t; }" : "=r"(a) : "l"(p));
    return a;
}
#define CP16(dst, src)  asm volatile("cp.async.cg.shared.global [%0], [%1], 16;" :: "r"(dst), "l"(src) : "memory")
#define CPCOMMIT()      asm volatile("cp.async.commit_group;" ::: "memory")
#define CPWAIT(n)       asm volatile("cp.async.wait_group %0;" :: "n"(n) : "memory")

#define LDSM4(r0,r1,r2,r3,addr) \
    asm volatile("ldmatrix.sync.aligned.m8n8.x4.shared.b16 {%0,%1,%2,%3}, [%4];" \
        : "=r"(r0),"=r"(r1),"=r"(r2),"=r"(r3) : "r"(addr))

#define MMA16816(d, a, b0, b1) \
    asm volatile("mma.sync.aligned.m16n8k16.row.col.f32.bf16.bf16.f32 " \
        "{%0,%1,%2,%3}, {%4,%5,%6,%7}, {%8,%9}, {%0,%1,%2,%3};" \
        : "+f"((d)[0]),"+f"((d)[1]),"+f"((d)[2]),"+f"((d)[3]) \
        : "r"((a)[0]),"r"((a)[1]),"r"((a)[2]),"r"((a)[3]), "r"(b0),"r"(b1))

__device__ __forceinline__ float flg2(float x){ float r; asm("lg2.approx.f32 %0, %1;" : "=f"(r) : "f"(x)); return r; }
__device__ __forceinline__ float fex2(float x){ float r; asm("ex2.approx.f32 %0, %1;" : "=f"(r) : "f"(x)); return r; }

// ---------- SMEM layout (per CTA, dynamic) ----------
// tgtA: 4 k-chunks x [64 rows x 128B] SW128            32768
// tgtB: +32768
// src:  2 stages x (A 8192 + B 8192), row-paired SW128 32768  @65536
// sPart: float[4][64]                                  1024   @98304
// sTsT:  float[64]                                     256    @99328
#define OFF_TGTA   0
#define OFF_TGTB   32768
#define OFF_SRC    65536
#define OFF_PART   98304
#define OFF_TST    99328
#define SMEM_BYTES 99584

// ---------- gather ----------
__global__ void gather_kernel(const int* __restrict__ skills, const int* __restrict__ problems,
                              const int* __restrict__ times,  const int* __restrict__ labels,
                              const float* __restrict__ aI, const float* __restrict__ aS,
                              const float* __restrict__ bI, const float* __restrict__ bS,
                              const float* __restrict__ pb, const float* __restrict__ sb)
{
    int idx = blockIdx.x * blockDim.x + threadIdx.x;
    if (idx >= NPOS * (EMB/4)) return;
    int pos = idx >> 6;
    int e   = (idx & 63) << 2;
    int sk  = skills[pos];
    int inter = sk + labels[pos] * NSK;
    float4 vA = *(const float4*)(aI + (size_t)inter*EMB + e);
    float4 vB = *(const float4*)(bI + (size_t)inter*EMB + e);
    float4 tA = *(const float4*)(aS + (size_t)sk*EMB + e);
    float4 tB = *(const float4*)(bS + (size_t)sk*EMB + e);
    size_t o = (size_t)pos*EMB + e;
    *(__nv_bfloat162*)(g_srcA + o)     = __floats2bfloat162_rn(vA.x, vA.y);
    *(__nv_bfloat162*)(g_srcA + o + 2) = __floats2bfloat162_rn(vA.z, vA.w);
    *(__nv_bfloat162*)(g_srcB + o)     = __floats2bfloat162_rn(vB.x, vB.y);
    *(__nv_bfloat162*)(g_srcB + o + 2) = __floats2bfloat162_rn(vB.z, vB.w);
    *(__nv_bfloat162*)(g_tgtA + o)     = __floats2bfloat162_rn(tA.x, tA.y);
    *(__nv_bfloat162*)(g_tgtA + o + 2) = __floats2bfloat162_rn(tA.z, tA.w);
    *(__nv_bfloat162*)(g_tgtB + o)     = __floats2bfloat162_rn(tB.x, tB.y);
    *(__nv_bfloat162*)(g_tgtB + o + 2) = __floats2bfloat162_rn(tB.z, tB.w);
    if ((idx & 63) == 0) {
        g_ts[pos]   = (float)times[pos] / 1000.0f;
        g_bias[pos] = pb[problems[pos]] + sb[sk];
    }
}

// issue one 128-row x K=32 src chunk (both matrices) into a stage.
// Row-paired layout: src row r -> 128B smem row (r>>1), 16B unit ug = (r&1)*4 + u',
// swizzled ug ^= ((r>>1)&7).
__device__ __forceinline__ void issue_src_chunk(uint32_t stage, int src_base, int kc8, int tid)
{
    #pragma unroll
    for (int rep = 0; rep < 4; ++rep) {
        int j   = tid + rep*256;          // 0..1023
        int mat = j >> 9;                 // 0: A, 1: B
        int rem = j & 511;
        int r2  = rem >> 3, ug = rem & 7;
        uint32_t dst = stage + mat*8192 + r2*128 + ((ug ^ (r2 & 7)) << 4);
        int row  = r2*2 + (ug >> 2);
        int ucol = ug & 3;
        const __nv_bfloat16* g = mat ? g_srcB : g_srcA;
        CP16(dst, g + (size_t)(src_base + row)*EMB + kc8*32 + ucol*8);
    }
}

// ---------- main HMMA kernel: 256 threads, 64 target cols, 2 CTAs/SM ----------
__global__ void __launch_bounds__(256, 2) hawkes_mma(float* __restrict__ out)
{
    extern __shared__ char smem[];
    const uint32_t sb = smem_u32(smem);
    const int tid  = threadIdx.x;
    const int wid  = tid >> 5;
    const int lane = tid & 31;
    const int wm   = wid >> 1;       // source-row group (32 rows)
    const int wn   = wid & 1;        // target-col group (32 cols)

    const int bidx = blockIdx.x;
    const int jt = (NT64 - 1) - (bidx >> 5);   // big tiles first
    const int b  = bidx & 31;
    const int col_base = b * S_LEN + jt * 64;  // global index of first target col
    const int it_max = jt >> 1;
    const int cOff = (jt & 1) * 64;            // diag-tile column offset

    float* sPart = (float*)(smem + OFF_PART);
    float* sTsT  = (float*)(smem + OFF_TST);

    // ---- prologue: resident target tiles + src chunks 0,1 ----
    {
        #pragma unroll
        for (int rep = 0; rep < 16; ++rep) {
            int j   = tid + rep*256;           // 0..4095
            int mat = j >> 11;                 // 0: tgtA, 1: tgtB
            int rem = j & 2047;
            int kc4 = rem >> 9;                // K-chunk (64 elems)
            int rr  = (rem >> 3) & 63;
            int u   = rem & 7;
            uint32_t dst = sb + (mat ? OFF_TGTB : OFF_TGTA) + kc4*8192 + rr*128 + ((u ^ (rr & 7)) << 4);
            const __nv_bfloat16* g = mat ? g_tgtB : g_tgtA;
            CP16(dst, g + (size_t)(col_base + rr)*EMB + kc4*64 + u*8);
        }
        issue_src_chunk(sb + OFF_SRC, b * S_LEN, 0, tid);
        CPCOMMIT();                                   // group: tgt + chunk0
        issue_src_chunk(sb + OFF_SRC + 16384, b * S_LEN, 1, tid);
        CPCOMMIT();                                   // group: chunk1
        if (tid < 64) sTsT[tid] = g_ts[col_base + tid];
        CPWAIT(1);
        __syncthreads();
    }

    // ---- per-lane constant addressing ----
    const int rA0 = wm*32 + (lane & 15);
    const int rA1 = rA0 + 16;
    const uint32_t offA0 = (uint32_t)(rA0 >> 1) * 128;
    const uint32_t offA1 = (uint32_t)(rA1 >> 1) * 128;
    const uint32_t xA0 = (uint32_t)(rA0 >> 1) & 7;
    const uint32_t xA1 = (uint32_t)(rA1 >> 1) & 7;
    const uint32_t ugA0 = (uint32_t)(rA0 & 1)*4 + (uint32_t)(lane >> 4);  // + kk*2
    const uint32_t ugA1 = (uint32_t)(rA1 & 1)*4 + (uint32_t)(lane >> 4);

    const int rB0 = wn*32 + (lane & 7) + ((lane >> 4) << 3);
    const int rB1 = rB0 + 16;
    const uint32_t offB0 = rB0*128, offB1 = rB1*128;
    const uint32_t xB0 = rB0 & 7,  xB1 = rB1 & 7;
    const uint32_t uBbit = (uint32_t)((lane >> 3) & 1);

    float colsum[4][2];
    #pragma unroll
    for (int n = 0; n < 4; ++n) { colsum[n][0] = 0.f; colsum[n][1] = 0.f; }

    const int G = (it_max + 1) * 8;
    const float NEG_INV_LN5 = -0.6213349345596119f;

    for (int it = 0; it <= it_max; ++it) {
        float accA[2][4][4], accB[2][4][4];
        #pragma unroll
        for (int m = 0; m < 2; ++m)
            #pragma unroll
            for (int n = 0; n < 4; ++n)
                #pragma unroll
                for (int e = 0; e < 4; ++e) { accA[m][n][e] = 0.f; accB[m][n][e] = 0.f; }

        #pragma unroll 1
        for (int kc8 = 0; kc8 < 8; ++kc8) {
            const int g = it*8 + kc8;
            const uint32_t stA = sb + OFF_SRC + (uint32_t)(g & 1)*16384;
            const uint32_t stB = stA + 8192;
            const uint32_t tgA = sb + OFF_TGTA + (uint32_t)(kc8 >> 1)*8192;
            const uint32_t tgB = sb + OFF_TGTB + (uint32_t)(kc8 >> 1)*8192;

            #pragma unroll
            for (int kk = 0; kk < 2; ++kk) {
                const uint32_t dA0 = ((ugA0 + kk*2) ^ xA0) << 4;
                const uint32_t dA1 = ((ugA1 + kk*2) ^ xA1) << 4;
                const uint32_t uB  = (((uint32_t)(kc8 & 1))*2 + (uint32_t)kk)*2 + uBbit;
                uint32_t aA0[4], aA1[4], aB0[4], aB1[4];
                uint32_t bA0[4], bA1[4], bB0[4], bB1[4];
                LDSM4(aA0[0],aA0[1],aA0[2],aA0[3], stA + offA0 + dA0);
                LDSM4(aA1[0],aA1[1],aA1[2],aA1[3], stA + offA1 + dA1);
                LDSM4(aB0[0],aB0[1],aB0[2],aB0[3], stB + offA0 + dA0);
                LDSM4(aB1[0],aB1[1],aB1[2],aB1[3], stB + offA1 + dA1);
                LDSM4(bA0[0],bA0[1],bA0[2],bA0[3], tgA + offB0 + (((uB ^ xB0)) << 4));
                LDSM4(bA1[0],bA1[1],bA1[2],bA1[3], tgA + offB1 + (((uB ^ xB1)) << 4));
                LDSM4(bB0[0],bB0[1],bB0[2],bB0[3], tgB + offB0 + (((uB ^ xB0)) << 4));
                LDSM4(bB1[0],bB1[1],bB1[2],bB1[3], tgB + offB1 + (((uB ^ xB1)) << 4));

                MMA16816(accA[0][0], aA0, bA0[0], bA0[1]);
                MMA16816(accA[0][1], aA0, bA0[2], bA0[3]);
                MMA16816(accA[0][2], aA0, bA1[0], bA1[1]);
                MMA16816(accA[0][3], aA0, bA1[2], bA1[3]);
                MMA16816(accA[1][0], aA1, bA0[0], bA0[1]);
                MMA16816(accA[1][1], aA1, bA0[2], bA0[3]);
                MMA16816(accA[1][2], aA1, bA1[0], bA1[1]);
                MMA16816(accA[1][3], aA1, bA1[2], bA1[3]);

                MMA16816(accB[0][0], aB0, bB0[0], bB0[1]);
                MMA16816(accB[0][1], aB0, bB0[2], bB0[3]);
                MMA16816(accB[0][2], aB0, bB1[0], bB1[1]);
                MMA16816(accB[0][3], aB0, bB1[2], bB1[3]);
                MMA16816(accB[1][0], aB1, bB0[0], bB0[1]);
                MMA16816(accB[1][1], aB1, bB0[2], bB0[3]);
                MMA16816(accB[1][2], aB1, bB1[0], bB1[1]);
                MMA16816(accB[1][3], aB1, bB1[2], bB1[3]);
            }

            __syncthreads();                          // all warps done reading stage g&1
            if (g + 2 < G) {
                const int gn = g + 2;
                issue_src_chunk(sb + OFF_SRC + (uint32_t)(gn & 1)*16384,
                                b * S_LEN + (gn >> 3)*128, gn & 7, tid);
            }
            CPCOMMIT();
            CPWAIT(1);                                // chunk g+1 resident
            __syncthreads();
        }

        // ---- epilogue for this source tile ----
        const int src_base = b * S_LEN + it * 128;
        const bool diag = (it == it_max);
        #pragma unroll
        for (int m = 0; m < 2; ++m) {
            const int rlo = wm*32 + m*16 + (lane >> 2);
            const float tsS_lo = g_ts[src_base + rlo];
            const float tsS_hi = g_ts[src_base + rlo + 8];
            #pragma unroll
            for (int n = 0; n < 4; ++n) {
                const int c0 = wn*32 + n*8 + 2*(lane & 3);
                #pragma unroll
                for (int e = 0; e < 4; ++e) {
                    const float tsS = (e < 2) ? tsS_lo : tsS_hi;
                    const int   r_l = (e < 2) ? rlo : rlo + 8;
                    const int   c_l = c0 + (e & 1);
                    float beta = fminf(fmaxf(accB[m][n][e] + 1.0f, 0.0f), 10.0f);
                    float d    = fabsf(tsS - sTsT[c_l]) + 1e-10f;
                    float L    = flg2(d);
                    float w    = fex2(beta * (L * NEG_INV_LN5));
                    float cr   = accA[m][n][e] * w;
                    if (!diag || (r_l < c_l + cOff)) colsum[n][e & 1] += cr;
                }
            }
        }
    }

    // ---- cross-lane column reduce (lanes sharing a column differ in lane>>2) ----
    #pragma unroll
    for (int n = 0; n < 4; ++n)
        #pragma unroll
        for (int p = 0; p < 2; ++p) {
            float v = colsum[n][p];
            v += __shfl_xor_sync(0xffffffffu, v, 4);
            v += __shfl_xor_sync(0xffffffffu, v, 8);
            v += __shfl_xor_sync(0xffffffffu, v, 16);
            colsum[n][p] = v;
        }
    __syncthreads();
    if (lane < 4) {
        #pragma unroll
        for (int n = 0; n < 4; ++n) {
            int c = wn*32 + n*8 + 2*lane;
            sPart[wm*64 + c]     = colsum[n][0];
            sPart[wm*64 + c + 1] = colsum[n][1];
        }
    }
    __syncthreads();

    if (tid < 64) {
        float s = sPart[tid] + sPart[64 + tid] + sPart[128 + tid] + sPart[192 + tid];
        float h = g_bias[col_base + tid] + s;
        out[col_base + tid] = 1.0f / (1.0f + fex2(-h * 1.4426950408889634f));
    }
}

extern "C" void kernel_launch(void* const* d_in, const int* in_sizes, int n_in,
                              void* d_out, int out_size)
{
    const int*   skills   = (const int*)d_in[0];
    const int*   problems = (const int*)d_in[1];
    const int*   times    = (const int*)d_in[2];
    const int*   labels   = (const int*)d_in[3];
    const float* aI = (const float*)d_in[4];
    const float* aS = (const float*)d_in[5];
    const float* bI = (const float*)d_in[6];
    const float* bS = (const float*)d_in[7];
    const float* pb = (const float*)d_in[8];
    const float* sb = (const float*)d_in[9];
    float* out = (float*)d_out;

    static bool attr_done = false;
    if (!attr_done) {
        cudaFuncSetAttribute(hawkes_mma, cudaFuncAttributeMaxDynamicSharedMemorySize, SMEM_BYTES);
        attr_done = true;
    }

    int total = NPOS * (EMB/4);
    gather_kernel<<<(total + 255) / 256, 256>>>(skills, problems, times, labels,
                                                aI, aS, bI, bS, pb, sb);
    hawkes_mma<<<NT64 * BB, 256, SMEM_BYTES>>>(out);
}